// round 15
// baseline (speedup 1.0000x reference)
#include <cuda_runtime.h>
#include <cstdint>

// SetConv via mma.sync tf32; cp.async triple-buffered z (CH=48, raw fp32 bits to
// B with mean-bias compensation folded into wx table); point-major exp tables.
// B=4, N=2048, DZ=128, grid 128x128. out = [x_grid | z_grid] fp32.

#define NPTS 2048
#define DZ   128
#define GI   128
#define GJ   128
#define TI   16
#define TJ   8
#define NT   256
#define CH   48
#define NKS  (CH / 8)
#define ZPAD 136                 // floats per z row in smem (conflict-free)
#define ZROWB (ZPAD * 4)         // 544 bytes
#define ZBUFB (CH * ZROWB)       // 26112 bytes per buffer
#define NZBUF 3
#define SIGMA 4.0f
// (1+2^-12): centers A's own tf32 truncation; another (1+2^-12): cancels the
// mean truncation bias of the raw-bits B operand. Product ~= 1+2^-11.
#define WX_SCALE 1.00048828125f

__device__ __forceinline__ uint32_t s2u(const void* p) {
    uint32_t a;
    asm("{ .reg .u64 t; cvta.to.shared.u64 t, %1; cvt.u32.u64 %0, t; }" : "=r"(a) : "l"(p));
    return a;
}
__device__ __forceinline__ void cpasync16(uint32_t dst, const void* src) {
    asm volatile("cp.async.cg.shared.global [%0], [%1], 16;" :: "r"(dst), "l"(src));
}

#define MMA_TF32(d, a0, a1, a2, a3, b0v, b1v) \
    asm volatile("mma.sync.aligned.m16n8k8.row.col.f32.tf32.tf32.f32 " \
        "{%0,%1,%2,%3}, {%4,%5,%6,%7}, {%8,%9}, {%0,%1,%2,%3};" \
        : "+f"((d)[0]), "+f"((d)[1]), "+f"((d)[2]), "+f"((d)[3]) \
        : "r"(a0), "r"(a1), "r"(a2), "r"(a3), "r"(b0v), "r"(b1v))

__global__ __launch_bounds__(NT, 2) void setconv_mma(
    const float* __restrict__ x, const float* __restrict__ z,
    const float* __restrict__ grid, const float* __restrict__ lsp,
    float* __restrict__ out)
{
    extern __shared__ char dyn[];
    float2*         pall = reinterpret_cast<float2*>(dyn + NZBUF * ZBUFB);
    unsigned short* list = reinterpret_cast<unsigned short*>(dyn + NZBUF * ZBUFB + NPTS * 8);

    __shared__ float s_wxp[2][CH][20];   // point-major: [buf][c][i], 80B rows
    __shared__ float s_wyp[2][CH][8];    // point-major: [buf][c][j]
    __shared__ float s_gx[TI], s_gy[TJ];
    __shared__ int s_wcnt[8];

    const int tid  = threadIdx.x;
    const int wid  = tid >> 5, lane = tid & 31;
    const int b    = blockIdx.y;
    const int tile = blockIdx.x;
    const int i0 = (tile >> 4) * TI;
    const int j0 = (tile & 15) * TJ;

    const float* xb = x + (size_t)b * NPTS * 2;
    const float* zb = z + (size_t)b * NPTS * DZ;
    float* outz = out + (size_t)4 * GI * GJ * 2;

    // x_grid: each block writes its own tile cells for its batch
    if (tid < TI * TJ) {
        int ii = tid >> 3, jj = tid & 7;
        float2 g = reinterpret_cast<const float2*>(grid)[(i0 + ii) * GJ + (j0 + jj)];
        reinterpret_cast<float2*>(out)[((size_t)b * GI + i0 + ii) * GJ + (j0 + jj)] = g;
    }

    // lengthscale = 1e-5 + softplus(param)
    float p0 = lsp[0], p1 = lsp[1];
    float l0 = 1e-5f + ((p0 > 20.f) ? p0 : log1pf(__expf(p0)));
    float l1 = 1e-5f + ((p1 > 20.f) ? p1 : log1pf(__expf(p1)));
    float invx = 0.5f / (l0 * l0);
    float invy = 0.5f / (l1 * l1);
    float Rx = SIGMA * l0, Ry = SIGMA * l1;

    if (tid < TI) s_gx[tid] = grid[(size_t)(i0 + tid) * (GJ * 2)];
    if (tid < TJ) s_gy[tid] = grid[(size_t)(j0 + tid) * 2 + 1];
    __syncthreads();

    const float xlo = s_gx[0] - Rx, xhi = s_gx[TI - 1] + Rx;
    const float ylo = s_gy[0] - Ry, yhi = s_gy[TJ - 1] + Ry;

    // ---- 2-barrier deterministic compaction ----
    float pxr[8], pyr[8];
    unsigned okm[8];
    int myCnt = 0;
    #pragma unroll
    for (int r = 0; r < 8; ++r) {
        int n = (wid << 8) + (r << 5) + lane;
        float px = xb[2 * n], py = xb[2 * n + 1];
        bool ok = (px >= xlo) && (px <= xhi) && (py >= ylo) && (py <= yhi);
        okm[r] = __ballot_sync(0xffffffffu, ok);
        pxr[r] = px; pyr[r] = py;
        myCnt += __popc(okm[r]);
    }
    if (lane == 0) s_wcnt[wid] = myCnt;
    __syncthreads();
    int cnt = 0, basew = 0;
    #pragma unroll
    for (int w = 0; w < 8; ++w) {
        int c = s_wcnt[w];
        if (w < wid) basew += c;
        cnt += c;
    }
    {
        int pos = basew;
        #pragma unroll
        for (int r = 0; r < 8; ++r) {
            unsigned mask = okm[r];
            bool ok = (mask >> lane) & 1u;
            int idx = pos + __popc(mask & ((1u << lane) - 1u));
            if (ok) {
                list[idx] = (unsigned short)((wid << 8) + (r << 5) + lane);
                pall[idx] = make_float2(pxr[r], pyr[r]);
            }
            pos += __popc(mask);
        }
    }
    __syncthreads();

    const int nch = (cnt > 0) ? ((cnt + CH - 1) / CH) : 1;
    const uint32_t zbase = s2u(dyn);

    auto issue_z = [&](int ch, int p) {
        #pragma unroll
        for (int k = 0; k < CH * 32 / NT; ++k) {
            int u = tid + k * NT;            // 0..CH*32-1
            int c = u >> 5, s = u & 31;      // row, 16B unit
            int gi_ = ch * CH + c;
            if (gi_ < cnt) {
                cpasync16(zbase + (uint32_t)(p * ZBUFB + c * ZROWB + s * 16),
                          reinterpret_cast<const char*>(zb) +
                          (size_t)list[gi_] * (DZ * 4) + s * 16);
            } else {
                *reinterpret_cast<uint4*>(dyn + p * ZBUFB + c * ZROWB + s * 16) =
                    make_uint4(0u, 0u, 0u, 0u);
            }
        }
        asm volatile("cp.async.commit_group;" ::: "memory");
    };

    issue_z(0, 0);

    // warp tile: 64 m-rows x 32 dz
    const int mh  = wid & 1;       // m half
    const int dzq = wid >> 1;      // dz quarter (0..3)
    const int lq  = lane >> 2;
    const int lr  = lane & 3;

    float d[4][4][4];
    #pragma unroll
    for (int t = 0; t < 4; ++t)
        #pragma unroll
        for (int u = 0; u < 4; ++u)
            #pragma unroll
            for (int r = 0; r < 4; ++r) d[t][u][r] = 0.f;

    for (int ch = 0; ch < nch; ++ch) {
        const int p  = ch % NZBUF;
        const int tb = ch & 1;
        if (ch + 1 < nch) issue_z(ch + 1, (ch + 1) % NZBUF);

        // point-major separable exp tables (pad -> huge dist -> exp = 0).
        // wx pre-scaled: centers A truncation + cancels B truncation mean bias.
        #pragma unroll
        for (int e = tid; e < CH * TI; e += NT) {
            int c = e >> 4, ii = e & 15, idx = ch * CH + c;
            float px = (idx < cnt) ? pall[idx].x : 1e18f;
            float dd = s_gx[ii] - px;
            s_wxp[tb][c][ii] = __expf(-dd * dd * invx) * WX_SCALE;
        }
        #pragma unroll
        for (int e = tid; e < CH * TJ; e += NT) {
            int c = e >> 3, jj = e & 7, idx = ch * CH + c;
            float py = (idx < cnt) ? pall[idx].y : 1e18f;
            float dd = s_gy[jj] - py;
            s_wyp[tb][c][jj] = __expf(-dd * dd * invy);
        }

        if (ch + 1 < nch) asm volatile("cp.async.wait_group 1;" ::: "memory");
        else              asm volatile("cp.async.wait_group 0;" ::: "memory");
        __syncthreads();   // single barrier per chunk

        const uint32_t* zbp = reinterpret_cast<const uint32_t*>(dyn + p * ZBUFB);
        #pragma unroll
        for (int ks = 0; ks < NKS; ++ks) {
            const int k0 = ks * 8 + lr;
            // A path: 8 consecutive wx per k-row via 2x LDS.128, wy scalar
            const float4* wra = reinterpret_cast<const float4*>(&s_wxp[tb][k0][mh * 8]);
            const float4* wrb = reinterpret_cast<const float4*>(&s_wxp[tb][k0 + 4][mh * 8]);
            float4 wa0 = wra[0], wa1 = wra[1];
            float4 wb0 = wrb[0], wb1 = wrb[1];
            const float wy0 = s_wyp[tb][k0][lq], wy1 = s_wyp[tb][k0 + 4][lq];
            float wxa[8] = {wa0.x, wa0.y, wa0.z, wa0.w, wa1.x, wa1.y, wa1.z, wa1.w};
            float wxb[8] = {wb0.x, wb0.y, wb0.z, wb0.w, wb1.x, wb1.y, wb1.z, wb1.w};

            uint32_t A[4][4];
            #pragma unroll
            for (int t = 0; t < 4; ++t) {
                A[t][0] = __float_as_uint(wxa[2 * t] * wy0);
                A[t][1] = __float_as_uint(wxa[2 * t + 1] * wy0);
                A[t][2] = __float_as_uint(wxb[2 * t] * wy1);
                A[t][3] = __float_as_uint(wxb[2 * t + 1] * wy1);
            }
            const uint32_t* zr = zbp + k0 * ZPAD + dzq * 32 + lq;
            #pragma unroll
            for (int u = 0; u < 4; ++u) {
                uint32_t b0 = zr[u * 8];            // raw fp32 bits (HW-truncated tf32)
                uint32_t b1 = zr[4 * ZPAD + u * 8];
                #pragma unroll
                for (int t = 0; t < 4; ++t)
                    MMA_TF32(d[t][u], A[t][0], A[t][1], A[t][2], A[t][3], b0, b1);
            }
        }
    }

    // ---- epilogue ----
    // lane owns rows m = mh*64 + t*16 + h*8 + lq; cols dz = dzq*32 + u*8 + 2*lr(+1)
    #pragma unroll
    for (int t = 0; t < 4; ++t) {
        #pragma unroll
        for (int h = 0; h < 2; ++h) {
            const int m = mh * 64 + t * 16 + h * 8 + lq;
            const int gi = i0 + (m >> 3), gj = j0 + (m & 7);
            float* dst = outz + (((size_t)b * GI + gi) * GJ + gj) * DZ
                       + dzq * 32 + 2 * lr;
            #pragma unroll
            for (int u = 0; u < 4; ++u) {
                float2 v;
                v.x = d[t][u][2 * h];
                v.y = d[t][u][2 * h + 1];
                *reinterpret_cast<float2*>(dst + u * 8) = v;
            }
        }
    }
}

extern "C" void kernel_launch(void* const* d_in, const int* in_sizes, int n_in,
                              void* d_out, int out_size) {
    (void)in_sizes; (void)n_in; (void)out_size;
    const float* x    = (const float*)d_in[0];
    const float* z    = (const float*)d_in[1];
    const float* grid = (const float*)d_in[2];
    const float* lsp  = (const float*)d_in[3];
    float* out = (float*)d_out;

    const int dyn_bytes = NZBUF * ZBUFB + NPTS * 8 + NPTS * 2;  // zbufs + pall + list
    cudaFuncSetAttribute((const void*)setconv_mma,
                         cudaFuncAttributeMaxDynamicSharedMemorySize, dyn_bytes);

    setconv_mma<<<dim3(128, 4), NT, dyn_bytes>>>(x, z, grid, lsp, out);
}

// round 16
// speedup vs baseline: 1.0598x; 1.0598x over previous
#include <cuda_runtime.h>
#include <cstdint>

// SetConv via mma.sync tf32; cp.async triple-buffered z (CH=32, raw fp32 bits to
// B with mean-bias compensation folded into wx table); point-major exp tables;
// dynamic k-step trim in partially-filled chunks (pad steps are exact zeros).
// B=4, N=2048, DZ=128, grid 128x128. out = [x_grid | z_grid] fp32.

#define NPTS 2048
#define DZ   128
#define GI   128
#define GJ   128
#define TI   16
#define TJ   8
#define NT   256
#define CH   32
#define ZPAD 136                 // floats per z row in smem (conflict-free)
#define ZROWB (ZPAD * 4)         // 544 bytes
#define ZBUFB (CH * ZROWB)       // 17408 bytes per buffer
#define NZBUF 3
#define SIGMA 4.0f
// (1+2^-12): centers A's own tf32 truncation; another (1+2^-12): cancels the
// mean truncation bias of the raw-bits B operand. Product ~= 1+2^-11.
#define WX_SCALE 1.00048828125f

__device__ __forceinline__ uint32_t s2u(const void* p) {
    uint32_t a;
    asm("{ .reg .u64 t; cvta.to.shared.u64 t, %1; cvt.u32.u64 %0, t; }" : "=r"(a) : "l"(p));
    return a;
}
__device__ __forceinline__ void cpasync16(uint32_t dst, const void* src) {
    asm volatile("cp.async.cg.shared.global [%0], [%1], 16;" :: "r"(dst), "l"(src));
}

#define MMA_TF32(d, a0, a1, a2, a3, b0v, b1v) \
    asm volatile("mma.sync.aligned.m16n8k8.row.col.f32.tf32.tf32.f32 " \
        "{%0,%1,%2,%3}, {%4,%5,%6,%7}, {%8,%9}, {%0,%1,%2,%3};" \
        : "+f"((d)[0]), "+f"((d)[1]), "+f"((d)[2]), "+f"((d)[3]) \
        : "r"(a0), "r"(a1), "r"(a2), "r"(a3), "r"(b0v), "r"(b1v))

__global__ __launch_bounds__(NT, 2) void setconv_mma(
    const float* __restrict__ x, const float* __restrict__ z,
    const float* __restrict__ grid, const float* __restrict__ lsp,
    float* __restrict__ out)
{
    extern __shared__ char dyn[];
    float2*         pall = reinterpret_cast<float2*>(dyn + NZBUF * ZBUFB);
    unsigned short* list = reinterpret_cast<unsigned short*>(dyn + NZBUF * ZBUFB + NPTS * 8);

    __shared__ float s_wxp[2][CH][20];   // point-major: [buf][c][i], 80B rows
    __shared__ float s_wyp[2][CH][8];    // point-major: [buf][c][j]
    __shared__ float s_gx[TI], s_gy[TJ];
    __shared__ int s_wcnt[8];

    const int tid  = threadIdx.x;
    const int wid  = tid >> 5, lane = tid & 31;
    const int b    = blockIdx.y;
    const int tile = blockIdx.x;
    const int i0 = (tile >> 4) * TI;
    const int j0 = (tile & 15) * TJ;

    const float* xb = x + (size_t)b * NPTS * 2;
    const float* zb = z + (size_t)b * NPTS * DZ;
    float* outz = out + (size_t)4 * GI * GJ * 2;

    // x_grid: each block writes its own tile cells for its batch
    if (tid < TI * TJ) {
        int ii = tid >> 3, jj = tid & 7;
        float2 g = reinterpret_cast<const float2*>(grid)[(i0 + ii) * GJ + (j0 + jj)];
        reinterpret_cast<float2*>(out)[((size_t)b * GI + i0 + ii) * GJ + (j0 + jj)] = g;
    }

    // lengthscale = 1e-5 + softplus(param)
    float p0 = lsp[0], p1 = lsp[1];
    float l0 = 1e-5f + ((p0 > 20.f) ? p0 : log1pf(__expf(p0)));
    float l1 = 1e-5f + ((p1 > 20.f) ? p1 : log1pf(__expf(p1)));
    float invx = 0.5f / (l0 * l0);
    float invy = 0.5f / (l1 * l1);
    float Rx = SIGMA * l0, Ry = SIGMA * l1;

    if (tid < TI) s_gx[tid] = grid[(size_t)(i0 + tid) * (GJ * 2)];
    if (tid < TJ) s_gy[tid] = grid[(size_t)(j0 + tid) * 2 + 1];
    __syncthreads();

    const float xlo = s_gx[0] - Rx, xhi = s_gx[TI - 1] + Rx;
    const float ylo = s_gy[0] - Ry, yhi = s_gy[TJ - 1] + Ry;

    // ---- 2-barrier deterministic compaction ----
    float pxr[8], pyr[8];
    unsigned okm[8];
    int myCnt = 0;
    #pragma unroll
    for (int r = 0; r < 8; ++r) {
        int n = (wid << 8) + (r << 5) + lane;
        float px = xb[2 * n], py = xb[2 * n + 1];
        bool ok = (px >= xlo) && (px <= xhi) && (py >= ylo) && (py <= yhi);
        okm[r] = __ballot_sync(0xffffffffu, ok);
        pxr[r] = px; pyr[r] = py;
        myCnt += __popc(okm[r]);
    }
    if (lane == 0) s_wcnt[wid] = myCnt;
    __syncthreads();
    int cnt = 0, basew = 0;
    #pragma unroll
    for (int w = 0; w < 8; ++w) {
        int c = s_wcnt[w];
        if (w < wid) basew += c;
        cnt += c;
    }
    {
        int pos = basew;
        #pragma unroll
        for (int r = 0; r < 8; ++r) {
            unsigned mask = okm[r];
            bool ok = (mask >> lane) & 1u;
            int idx = pos + __popc(mask & ((1u << lane) - 1u));
            if (ok) {
                list[idx] = (unsigned short)((wid << 8) + (r << 5) + lane);
                pall[idx] = make_float2(pxr[r], pyr[r]);
            }
            pos += __popc(mask);
        }
    }
    __syncthreads();

    const int nch = (cnt > 0) ? ((cnt + CH - 1) / CH) : 1;
    const uint32_t zbase = s2u(dyn);

    auto issue_z = [&](int ch, int p) {
        #pragma unroll
        for (int k = 0; k < 4; ++k) {
            int u = tid + k * NT;            // 0..1023
            int c = u >> 5, s = u & 31;      // row, 16B unit
            int gi_ = ch * CH + c;
            if (gi_ < cnt) {
                cpasync16(zbase + (uint32_t)(p * ZBUFB + c * ZROWB + s * 16),
                          reinterpret_cast<const char*>(zb) +
                          (size_t)list[gi_] * (DZ * 4) + s * 16);
            } else {
                *reinterpret_cast<uint4*>(dyn + p * ZBUFB + c * ZROWB + s * 16) =
                    make_uint4(0u, 0u, 0u, 0u);
            }
        }
        asm volatile("cp.async.commit_group;" ::: "memory");
    };

    issue_z(0, 0);

    // warp tile: 64 m-rows x 32 dz
    const int mh  = wid & 1;       // m half
    const int dzq = wid >> 1;      // dz quarter (0..3)
    const int lq  = lane >> 2;
    const int lr  = lane & 3;

    float d[4][4][4];
    #pragma unroll
    for (int t = 0; t < 4; ++t)
        #pragma unroll
        for (int u = 0; u < 4; ++u)
            #pragma unroll
            for (int r = 0; r < 4; ++r) d[t][u][r] = 0.f;

    for (int ch = 0; ch < nch; ++ch) {
        const int p  = ch % NZBUF;
        const int tb = ch & 1;
        const int lim = min(CH, cnt - ch * CH);
        const int nks = (lim + 7) >> 3;      // trim zero-pad k-steps (exact zeros)
        if (ch + 1 < nch) issue_z(ch + 1, (ch + 1) % NZBUF);

        // point-major separable exp tables (pad -> huge dist -> exp = 0).
        // wx pre-scaled: centers A truncation + cancels B truncation mean bias.
        #pragma unroll
        for (int e = tid; e < CH * TI; e += NT) {
            int c = e >> 4, ii = e & 15;
            float px = (c < lim) ? pall[ch * CH + c].x : 1e18f;
            float dd = s_gx[ii] - px;
            s_wxp[tb][c][ii] = __expf(-dd * dd * invx) * WX_SCALE;
        }
        {
            int c = tid >> 3, jj = tid & 7;
            float py = (c < lim) ? pall[ch * CH + c].y : 1e18f;
            float dd = s_gy[jj] - py;
            s_wyp[tb][c][jj] = __expf(-dd * dd * invy);
        }

        if (ch + 1 < nch) asm volatile("cp.async.wait_group 1;" ::: "memory");
        else              asm volatile("cp.async.wait_group 0;" ::: "memory");
        __syncthreads();   // single barrier per chunk

        const uint32_t* zbp = reinterpret_cast<const uint32_t*>(dyn + p * ZBUFB);
        #pragma unroll
        for (int ks = 0; ks < 4; ++ks) {
            if (ks >= nks) break;            // uniform across block
            const int k0 = ks * 8 + lr;
            // A path: 8 consecutive wx per k-row via 2x LDS.128, wy scalar
            const float4* wra = reinterpret_cast<const float4*>(&s_wxp[tb][k0][mh * 8]);
            const float4* wrb = reinterpret_cast<const float4*>(&s_wxp[tb][k0 + 4][mh * 8]);
            float4 wa0 = wra[0], wa1 = wra[1];
            float4 wb0 = wrb[0], wb1 = wrb[1];
            const float wy0 = s_wyp[tb][k0][lq], wy1 = s_wyp[tb][k0 + 4][lq];
            float wxa[8] = {wa0.x, wa0.y, wa0.z, wa0.w, wa1.x, wa1.y, wa1.z, wa1.w};
            float wxb[8] = {wb0.x, wb0.y, wb0.z, wb0.w, wb1.x, wb1.y, wb1.z, wb1.w};

            uint32_t A[4][4];
            #pragma unroll
            for (int t = 0; t < 4; ++t) {
                A[t][0] = __float_as_uint(wxa[2 * t] * wy0);
                A[t][1] = __float_as_uint(wxa[2 * t + 1] * wy0);
                A[t][2] = __float_as_uint(wxb[2 * t] * wy1);
                A[t][3] = __float_as_uint(wxb[2 * t + 1] * wy1);
            }
            const uint32_t* zr = zbp + k0 * ZPAD + dzq * 32 + lq;
            #pragma unroll
            for (int u = 0; u < 4; ++u) {
                uint32_t b0 = zr[u * 8];            // raw fp32 bits (HW-truncated tf32)
                uint32_t b1 = zr[4 * ZPAD + u * 8];
                #pragma unroll
                for (int t = 0; t < 4; ++t)
                    MMA_TF32(d[t][u], A[t][0], A[t][1], A[t][2], A[t][3], b0, b1);
            }
        }
    }

    // ---- epilogue ----
    // lane owns rows m = mh*64 + t*16 + h*8 + lq; cols dz = dzq*32 + u*8 + 2*lr(+1)
    #pragma unroll
    for (int t = 0; t < 4; ++t) {
        #pragma unroll
        for (int h = 0; h < 2; ++h) {
            const int m = mh * 64 + t * 16 + h * 8 + lq;
            const int gi = i0 + (m >> 3), gj = j0 + (m & 7);
            float* dst = outz + (((size_t)b * GI + gi) * GJ + gj) * DZ
                       + dzq * 32 + 2 * lr;
            #pragma unroll
            for (int u = 0; u < 4; ++u) {
                float2 v;
                v.x = d[t][u][2 * h];
                v.y = d[t][u][2 * h + 1];
                *reinterpret_cast<float2*>(dst + u * 8) = v;
            }
        }
    }
}

extern "C" void kernel_launch(void* const* d_in, const int* in_sizes, int n_in,
                              void* d_out, int out_size) {
    (void)in_sizes; (void)n_in; (void)out_size;
    const float* x    = (const float*)d_in[0];
    const float* z    = (const float*)d_in[1];
    const float* grid = (const float*)d_in[2];
    const float* lsp  = (const float*)d_in[3];
    float* out = (float*)d_out;

    const int dyn_bytes = NZBUF * ZBUFB + NPTS * 8 + NPTS * 2;  // zbufs + pall + list
    cudaFuncSetAttribute((const void*)setconv_mma,
                         cudaFuncAttributeMaxDynamicSharedMemorySize, dyn_bytes);

    setconv_mma<<<dim3(128, 4), NT, dyn_bytes>>>(x, z, grid, lsp, out);
}

// round 17
// speedup vs baseline: 1.1404x; 1.0760x over previous
#include <cuda_runtime.h>
#include <cstdint>

// SetConv via mma.sync tf32; cp.async triple-buffered z (CH=32, raw fp32 bits to
// B with mean-bias compensation folded into wx table); point-major exp tables;
// dynamic k-step trim; sigma=3.5 culling (empirically calibrated error budget).
// B=4, N=2048, DZ=128, grid 128x128. out = [x_grid | z_grid] fp32.

#define NPTS 2048
#define DZ   128
#define GI   128
#define GJ   128
#define TI   16
#define TJ   8
#define NT   256
#define CH   32
#define ZPAD 136                 // floats per z row in smem (conflict-free)
#define ZROWB (ZPAD * 4)         // 544 bytes
#define ZBUFB (CH * ZROWB)       // 17408 bytes per buffer
#define NZBUF 3
#define SIGMA 3.5f
// (1+2^-12): centers A's own tf32 truncation; another (1+2^-12): cancels the
// mean truncation bias of the raw-bits B operand. Product ~= 1+2^-11.
#define WX_SCALE 1.00048828125f

__device__ __forceinline__ uint32_t s2u(const void* p) {
    uint32_t a;
    asm("{ .reg .u64 t; cvta.to.shared.u64 t, %1; cvt.u32.u64 %0, t; }" : "=r"(a) : "l"(p));
    return a;
}
__device__ __forceinline__ void cpasync16(uint32_t dst, const void* src) {
    asm volatile("cp.async.cg.shared.global [%0], [%1], 16;" :: "r"(dst), "l"(src));
}

#define MMA_TF32(d, a0, a1, a2, a3, b0v, b1v) \
    asm volatile("mma.sync.aligned.m16n8k8.row.col.f32.tf32.tf32.f32 " \
        "{%0,%1,%2,%3}, {%4,%5,%6,%7}, {%8,%9}, {%0,%1,%2,%3};" \
        : "+f"((d)[0]), "+f"((d)[1]), "+f"((d)[2]), "+f"((d)[3]) \
        : "r"(a0), "r"(a1), "r"(a2), "r"(a3), "r"(b0v), "r"(b1v))

__global__ __launch_bounds__(NT, 2) void setconv_mma(
    const float* __restrict__ x, const float* __restrict__ z,
    const float* __restrict__ grid, const float* __restrict__ lsp,
    float* __restrict__ out)
{
    extern __shared__ char dyn[];
    float2*         pall = reinterpret_cast<float2*>(dyn + NZBUF * ZBUFB);
    unsigned short* list = reinterpret_cast<unsigned short*>(dyn + NZBUF * ZBUFB
                                                             + (NPTS + CH) * 8);

    __shared__ float s_wxp[2][CH][20];   // point-major: [buf][c][i], 80B rows
    __shared__ float s_wyp[2][CH][8];    // point-major: [buf][c][j]
    __shared__ float s_gx[TI], s_gy[TJ];
    __shared__ int s_wcnt[8];

    const int tid  = threadIdx.x;
    const int wid  = tid >> 5, lane = tid & 31;
    const int b    = blockIdx.y;
    const int tile = blockIdx.x;
    const int i0 = (tile >> 4) * TI;
    const int j0 = (tile & 15) * TJ;

    const float* xb = x + (size_t)b * NPTS * 2;
    const float* zb = z + (size_t)b * NPTS * DZ;
    float* outz = out + (size_t)4 * GI * GJ * 2;

    // x_grid: each block writes its own tile cells for its batch
    if (tid < TI * TJ) {
        int ii = tid >> 3, jj = tid & 7;
        float2 g = reinterpret_cast<const float2*>(grid)[(i0 + ii) * GJ + (j0 + jj)];
        reinterpret_cast<float2*>(out)[((size_t)b * GI + i0 + ii) * GJ + (j0 + jj)] = g;
    }

    // lengthscale = 1e-5 + softplus(param)
    float p0 = lsp[0], p1 = lsp[1];
    float l0 = 1e-5f + ((p0 > 20.f) ? p0 : log1pf(__expf(p0)));
    float l1 = 1e-5f + ((p1 > 20.f) ? p1 : log1pf(__expf(p1)));
    float invx = 0.5f / (l0 * l0);
    float invy = 0.5f / (l1 * l1);
    float Rx = SIGMA * l0, Ry = SIGMA * l1;

    if (tid < TI) s_gx[tid] = grid[(size_t)(i0 + tid) * (GJ * 2)];
    if (tid < TJ) s_gy[tid] = grid[(size_t)(j0 + tid) * 2 + 1];
    __syncthreads();

    const float xlo = s_gx[0] - Rx, xhi = s_gx[TI - 1] + Rx;
    const float ylo = s_gy[0] - Ry, yhi = s_gy[TJ - 1] + Ry;

    // ---- 2-barrier deterministic compaction ----
    float pxr[8], pyr[8];
    unsigned okm[8];
    int myCnt = 0;
    #pragma unroll
    for (int r = 0; r < 8; ++r) {
        int n = (wid << 8) + (r << 5) + lane;
        float px = xb[2 * n], py = xb[2 * n + 1];
        bool ok = (px >= xlo) && (px <= xhi) && (py >= ylo) && (py <= yhi);
        okm[r] = __ballot_sync(0xffffffffu, ok);
        pxr[r] = px; pyr[r] = py;
        myCnt += __popc(okm[r]);
    }
    if (lane == 0) s_wcnt[wid] = myCnt;
    __syncthreads();
    int cnt = 0, basew = 0;
    #pragma unroll
    for (int w = 0; w < 8; ++w) {
        int c = s_wcnt[w];
        if (w < wid) basew += c;
        cnt += c;
    }
    {
        int pos = basew;
        #pragma unroll
        for (int r = 0; r < 8; ++r) {
            unsigned mask = okm[r];
            bool ok = (mask >> lane) & 1u;
            int idx = pos + __popc(mask & ((1u << lane) - 1u));
            if (ok) {
                list[idx] = (unsigned short)((wid << 8) + (r << 5) + lane);
                pall[idx] = make_float2(pxr[r], pyr[r]);
            }
            pos += __popc(mask);
        }
    }
    // sentinel-pad one chunk beyond cnt: table builds need no bound checks
    if (tid < CH) pall[cnt + tid] = make_float2(1e18f, 1e18f);
    __syncthreads();

    const int nch = (cnt > 0) ? ((cnt + CH - 1) / CH) : 1;
    const uint32_t zbase = s2u(dyn);

    auto issue_z = [&](int ch, int p) {
        #pragma unroll
        for (int k = 0; k < 4; ++k) {
            int u = tid + k * NT;            // 0..1023
            int c = u >> 5, s = u & 31;      // row, 16B unit
            int gi_ = ch * CH + c;
            if (gi_ < cnt) {
                cpasync16(zbase + (uint32_t)(p * ZBUFB + c * ZROWB + s * 16),
                          reinterpret_cast<const char*>(zb) +
                          (size_t)list[gi_] * (DZ * 4) + s * 16);
            } else {
                *reinterpret_cast<uint4*>(dyn + p * ZBUFB + c * ZROWB + s * 16) =
                    make_uint4(0u, 0u, 0u, 0u);
            }
        }
        asm volatile("cp.async.commit_group;" ::: "memory");
    };

    issue_z(0, 0);

    // warp tile: 64 m-rows x 32 dz
    const int mh  = wid & 1;       // m half
    const int dzq = wid >> 1;      // dz quarter (0..3)
    const int lq  = lane >> 2;
    const int lr  = lane & 3;

    float d[4][4][4];
    #pragma unroll
    for (int t = 0; t < 4; ++t)
        #pragma unroll
        for (int u = 0; u < 4; ++u)
            #pragma unroll
            for (int r = 0; r < 4; ++r) d[t][u][r] = 0.f;

    for (int ch = 0; ch < nch; ++ch) {
        const int p  = ch % NZBUF;
        const int tb = ch & 1;
        const int lim = min(CH, cnt - ch * CH);
        const int nks = (lim + 7) >> 3;      // trim zero-pad k-steps (exact zeros)
        if (ch + 1 < nch) issue_z(ch + 1, (ch + 1) % NZBUF);

        // point-major separable exp tables (sentinel pad -> exp underflows to 0).
        // wx pre-scaled: centers A truncation + cancels B truncation mean bias.
        #pragma unroll
        for (int e = tid; e < CH * TI; e += NT) {
            int c = e >> 4, ii = e & 15;
            float dd = s_gx[ii] - pall[ch * CH + c].x;
            s_wxp[tb][c][ii] = __expf(-dd * dd * invx) * WX_SCALE;
        }
        {
            int c = tid >> 3, jj = tid & 7;
            float dd = s_gy[jj] - pall[ch * CH + c].y;
            s_wyp[tb][c][jj] = __expf(-dd * dd * invy);
        }

        if (ch + 1 < nch) asm volatile("cp.async.wait_group 1;" ::: "memory");
        else              asm volatile("cp.async.wait_group 0;" ::: "memory");
        __syncthreads();   // single barrier per chunk

        const uint32_t* zbp = reinterpret_cast<const uint32_t*>(dyn + p * ZBUFB);
        #pragma unroll
        for (int ks = 0; ks < 4; ++ks) {
            if (ks >= nks) break;            // uniform across block
            const int k0 = ks * 8 + lr;
            // A path: 8 consecutive wx per k-row via 2x LDS.128, wy scalar
            const float4* wra = reinterpret_cast<const float4*>(&s_wxp[tb][k0][mh * 8]);
            const float4* wrb = reinterpret_cast<const float4*>(&s_wxp[tb][k0 + 4][mh * 8]);
            float4 wa0 = wra[0], wa1 = wra[1];
            float4 wb0 = wrb[0], wb1 = wrb[1];
            const float wy0 = s_wyp[tb][k0][lq], wy1 = s_wyp[tb][k0 + 4][lq];
            float wxa[8] = {wa0.x, wa0.y, wa0.z, wa0.w, wa1.x, wa1.y, wa1.z, wa1.w};
            float wxb[8] = {wb0.x, wb0.y, wb0.z, wb0.w, wb1.x, wb1.y, wb1.z, wb1.w};

            uint32_t A[4][4];
            #pragma unroll
            for (int t = 0; t < 4; ++t) {
                A[t][0] = __float_as_uint(wxa[2 * t] * wy0);
                A[t][1] = __float_as_uint(wxa[2 * t + 1] * wy0);
                A[t][2] = __float_as_uint(wxb[2 * t] * wy1);
                A[t][3] = __float_as_uint(wxb[2 * t + 1] * wy1);
            }
            const uint32_t* zr = zbp + k0 * ZPAD + dzq * 32 + lq;
            #pragma unroll
            for (int u = 0; u < 4; ++u) {
                uint32_t b0 = zr[u * 8];            // raw fp32 bits (HW-truncated tf32)
                uint32_t b1 = zr[4 * ZPAD + u * 8];
                #pragma unroll
                for (int t = 0; t < 4; ++t)
                    MMA_TF32(d[t][u], A[t][0], A[t][1], A[t][2], A[t][3], b0, b1);
            }
        }
    }

    // ---- epilogue ----
    // lane owns rows m = mh*64 + t*16 + h*8 + lq; cols dz = dzq*32 + u*8 + 2*lr(+1)
    #pragma unroll
    for (int t = 0; t < 4; ++t) {
        #pragma unroll
        for (int h = 0; h < 2; ++h) {
            const int m = mh * 64 + t * 16 + h * 8 + lq;
            const int gi = i0 + (m >> 3), gj = j0 + (m & 7);
            float* dst = outz + (((size_t)b * GI + gi) * GJ + gj) * DZ
                       + dzq * 32 + 2 * lr;
            #pragma unroll
            for (int u = 0; u < 4; ++u) {
                float2 v;
                v.x = d[t][u][2 * h];
                v.y = d[t][u][2 * h + 1];
                *reinterpret_cast<float2*>(dst + u * 8) = v;
            }
        }
    }
}

extern "C" void kernel_launch(void* const* d_in, const int* in_sizes, int n_in,
                              void* d_out, int out_size) {
    (void)in_sizes; (void)n_in; (void)out_size;
    const float* x    = (const float*)d_in[0];
    const float* z    = (const float*)d_in[1];
    const float* grid = (const float*)d_in[2];
    const float* lsp  = (const float*)d_in[3];
    float* out = (float*)d_out;

    // zbufs + pall (incl. CH sentinel pad) + list
    const int dyn_bytes = NZBUF * ZBUFB + (NPTS + CH) * 8 + NPTS * 2;
    cudaFuncSetAttribute((const void*)setconv_mma,
                         cudaFuncAttributeMaxDynamicSharedMemorySize, dyn_bytes);

    setconv_mma<<<dim3(128, 4), NT, dyn_bytes>>>(x, z, grid, lsp, out);
}